// round 12
// baseline (speedup 1.0000x reference)
#include <cuda_runtime.h>

// TemporalAttention_43722767073503 — CONVERGED (final)
//
// Reference output = log_softmax over a size-1 last axis of the (B,T,1) score
// tensor -> identically 0 for every finite input (x - logsumexp(x) = 0).
// Both GEMMs, the tanh, and the v-projection are dead code; the exact answer
// is 524288 f32 zeros. rel_err = 0 exactly.
//
// Measured floor (6 passing runs, 3 geometries, 4 byte-identical reruns):
// kernel 3.74-4.00us, wall 5.06-6.02us, DRAM 0%, L2 ~5%, issue 5-7%. The 2MB
// of stores costs ~330 cycles; the rest is the fixed per-launch overhead
// floor plus graph-replay overhead and run-to-run jitter (~0.9us wall spread
// on an unchanged binary). No kernel-side lever remains; resubmitting the
// best-measured binary unchanged.
//
// Configuration: 512 CTAs x 256 threads, one unconditional STG.128 per thread
// (512*256*4 = 524288 floats, exact cover — no bounds check, loop, or tail).

__global__ void zero_exact_512x256(float4* __restrict__ out) {
    out[blockIdx.x * blockDim.x + threadIdx.x] =
        make_float4(0.f, 0.f, 0.f, 0.f);
}

// General fallback (never taken for this problem's out_size; safety only).
__global__ void zero_general(float* __restrict__ out, int n) {
    for (int i = blockIdx.x * blockDim.x + threadIdx.x; i < n;
         i += gridDim.x * blockDim.x) {
        out[i] = 0.f;
    }
}

extern "C" void kernel_launch(void* const* d_in, const int* in_sizes, int n_in,
                              void* d_out, int out_size) {
    (void)d_in; (void)in_sizes; (void)n_in;

    const int threads = 256;
    int n4 = out_size >> 2;
    if ((out_size & 3) == 0 && (n4 % threads) == 0) {
        zero_exact_512x256<<<n4 / threads, threads>>>((float4*)d_out);
    } else {
        int blocks = (out_size + threads - 1) / threads;
        if (blocks > 1024) blocks = 1024;
        zero_general<<<blocks, threads>>>((float*)d_out, out_size);
    }
}

// round 13
// speedup vs baseline: 1.1813x; 1.1813x over previous
#include <cuda_runtime.h>

// TemporalAttention_43722767073503 — CONVERGED (final)
//
// Reference output = log_softmax over a size-1 last axis of the (B,T,1) score
// tensor -> identically 0 for every finite input (x - logsumexp(x) = 0).
// Both GEMMs, the tanh, and the v-projection are dead code; the exact answer
// is 524288 f32 zeros. rel_err = 0 exactly.
//
// Measured floor (7 passing runs, 3 geometries, 5 byte-identical reruns):
// kernel 3.74-4.00us, wall 5.06-6.05us, DRAM 0%, L2 ~5%, issue 5-7%. The 2MB
// of stores costs ~330 cycles; the rest is the fixed per-launch overhead
// floor plus graph-replay overhead and run-to-run jitter. No kernel-side
// lever remains; resubmitting the best-measured binary unchanged.
//
// Configuration: 512 CTAs x 256 threads, one unconditional STG.128 per thread
// (512*256*4 = 524288 floats, exact cover — no bounds check, loop, or tail).

__global__ void zero_exact_512x256(float4* __restrict__ out) {
    out[blockIdx.x * blockDim.x + threadIdx.x] =
        make_float4(0.f, 0.f, 0.f, 0.f);
}

// General fallback (never taken for this problem's out_size; safety only).
__global__ void zero_general(float* __restrict__ out, int n) {
    for (int i = blockIdx.x * blockDim.x + threadIdx.x; i < n;
         i += gridDim.x * blockDim.x) {
        out[i] = 0.f;
    }
}

extern "C" void kernel_launch(void* const* d_in, const int* in_sizes, int n_in,
                              void* d_out, int out_size) {
    (void)d_in; (void)in_sizes; (void)n_in;

    const int threads = 256;
    int n4 = out_size >> 2;
    if ((out_size & 3) == 0 && (n4 % threads) == 0) {
        zero_exact_512x256<<<n4 / threads, threads>>>((float4*)d_out);
    } else {
        int blocks = (out_size + threads - 1) / threads;
        if (blocks > 1024) blocks = 1024;
        zero_general<<<blocks, threads>>>((float*)d_out, out_size);
    }
}

// round 14
// speedup vs baseline: 1.1887x; 1.0063x over previous
#include <cuda_runtime.h>

// TemporalAttention_43722767073503 — CONVERGED (final)
//
// Reference output = log_softmax over a size-1 last axis of the (B,T,1) score
// tensor -> identically 0 for every finite input (x - logsumexp(x) = 0).
// Both GEMMs, the tanh, and the v-projection are dead code; the exact answer
// is 524288 f32 zeros. rel_err = 0 exactly.
//
// Measured floor (8 passing runs, 3 geometries, 6 byte-identical reruns):
// kernel 3.74-4.00us, wall 5.06-6.05us, DRAM 0%, L2 ~5%, issue 5-7%. The 2MB
// of stores costs ~330 cycles; the rest is the fixed per-launch overhead
// floor plus graph-replay overhead and run-to-run jitter. No kernel-side
// lever remains; resubmitting the best-measured binary unchanged.
//
// Configuration: 512 CTAs x 256 threads, one unconditional STG.128 per thread
// (512*256*4 = 524288 floats, exact cover — no bounds check, loop, or tail).

__global__ void zero_exact_512x256(float4* __restrict__ out) {
    out[blockIdx.x * blockDim.x + threadIdx.x] =
        make_float4(0.f, 0.f, 0.f, 0.f);
}

// General fallback (never taken for this problem's out_size; safety only).
__global__ void zero_general(float* __restrict__ out, int n) {
    for (int i = blockIdx.x * blockDim.x + threadIdx.x; i < n;
         i += gridDim.x * blockDim.x) {
        out[i] = 0.f;
    }
}

extern "C" void kernel_launch(void* const* d_in, const int* in_sizes, int n_in,
                              void* d_out, int out_size) {
    (void)d_in; (void)in_sizes; (void)n_in;

    const int threads = 256;
    int n4 = out_size >> 2;
    if ((out_size & 3) == 0 && (n4 % threads) == 0) {
        zero_exact_512x256<<<n4 / threads, threads>>>((float4*)d_out);
    } else {
        int blocks = (out_size + threads - 1) / threads;
        if (blocks > 1024) blocks = 1024;
        zero_general<<<blocks, threads>>>((float*)d_out, out_size);
    }
}